// round 10
// baseline (speedup 1.0000x reference)
#include <cuda_runtime.h>
#include <cuda_bf16.h>
#include <math.h>
#include <stdint.h>

#define NN 40000
#define NE 640000

// ---------------- scratch (device globals: allocation-free) ----------------
__device__ int   g_is64;
__device__ int   g_src[NE];
__device__ int   g_dst[NE];
__device__ int   g_csr[NE];
__device__ int   g_deg[NN];
__device__ int   g_fill[NN];
__device__ int   g_off[NN + 1];
__device__ float g_h[NN * 128];
__device__ float g_yr[NN * 128];
__device__ float g_base[NN * 128];
// packed weights, all 3 layers: [n][k] K-major bf16 hi/lo
// region offsets (elements): L0=0 (256 rows), L1=32768 (256 rows), L2=65536 (128 rows)
__device__ __nv_bfloat16 g_Bh[640 * 128];
__device__ __nv_bfloat16 g_Bl[640 * 128];

// ---------------- helpers ----------------
__device__ __forceinline__ uint32_t smem_u32(const void* p) {
    uint32_t a;
    asm("{ .reg .u64 t; cvta.to.shared.u64 t, %1; cvt.u32.u64 %0, t; }"
        : "=r"(a) : "l"(p));
    return a;
}

__device__ __forceinline__ void ldsm4(uint32_t& r0, uint32_t& r1,
                                      uint32_t& r2, uint32_t& r3, uint32_t addr) {
    asm volatile("ldmatrix.sync.aligned.m8n8.x4.shared.b16 {%0,%1,%2,%3}, [%4];"
                 : "=r"(r0), "=r"(r1), "=r"(r2), "=r"(r3) : "r"(addr));
}

__device__ __forceinline__ void mma_bf16(float* d, const uint32_t* a,
                                         uint32_t b0, uint32_t b1) {
    asm volatile(
        "mma.sync.aligned.m16n8k16.row.col.f32.bf16.bf16.f32 "
        "{%0,%1,%2,%3}, {%4,%5,%6,%7}, {%8,%9}, {%0,%1,%2,%3};"
        : "+f"(d[0]), "+f"(d[1]), "+f"(d[2]), "+f"(d[3])
        : "r"(a[0]), "r"(a[1]), "r"(a[2]), "r"(a[3]), "r"(b0), "r"(b1));
}

// ---------------- edge dtype detection ----------------
// int64 little-endian with values < 40000 -> every odd 32-bit word is 0.
__global__ void detect_kernel(const int* __restrict__ e32) {
    if (threadIdx.x == 0) {
        int ok = 1;
        for (int i = 0; i < 64; i++)
            if (e32[2 * i + 1] != 0) { ok = 0; break; }
        g_is64 = ok;
    }
}

__global__ void zero_kernel() {
    int i = blockIdx.x * blockDim.x + threadIdx.x;
    if (i < NN) { g_deg[i] = 0; g_fill[i] = 0; }
}

// convert + histogram fused (zero_kernel must precede)
__global__ void convert_hist_kernel(const void* __restrict__ ei) {
    int e = blockIdx.x * blockDim.x + threadIdx.x;
    if (e >= NE) return;
    int s, d;
    if (g_is64) {
        const long long* p = (const long long*)ei;
        s = (int)p[e]; d = (int)p[NE + e];
    } else {
        const int* p = (const int*)ei;
        s = p[e]; d = p[NE + e];
    }
    g_src[e] = s;
    g_dst[e] = d;
    atomicAdd(&g_deg[d], 1);
}

// shfl-based exclusive scan over g_deg -> g_off (single block, 1024 threads)
__global__ void scan_kernel() {
    __shared__ int wsum[32];
    __shared__ int carry_s;
    int t = threadIdx.x, lane = t & 31, wi = t >> 5;
    if (t == 0) carry_s = 0;
    __syncthreads();
    for (int base = 0; base < NN; base += 1024) {
        int v = (base + t < NN) ? g_deg[base + t] : 0;
        int x = v;
        #pragma unroll
        for (int o = 1; o < 32; o <<= 1) {
            int y = __shfl_up_sync(0xffffffffu, x, o);
            if (lane >= o) x += y;
        }
        if (lane == 31) wsum[wi] = x;
        __syncthreads();                       // S1: wsum[] published
        if (wi == 0) {
            int s = wsum[lane];
            #pragma unroll
            for (int o = 1; o < 32; o <<= 1) {
                int y = __shfl_up_sync(0xffffffffu, s, o);
                if (lane >= o) s += y;
            }
            wsum[lane] = s;                    // inclusive scan of warp sums
        }
        __syncthreads();                       // S2: scanned wsum published
        int warpoff = (wi > 0) ? wsum[wi - 1] : 0;
        int carry = carry_s;
        if (base + t < NN) g_off[base + t] = carry + warpoff + x - v;
        __syncthreads();                       // S3: all reads done
        if (t == 1023) carry_s = carry + wsum[31];
        __syncthreads();                       // S4: carry visible, wsum reusable
    }
    if (threadIdx.x == 0) g_off[NN] = carry_s;
}

__global__ void fill_kernel() {
    int e = blockIdx.x * blockDim.x + threadIdx.x;
    if (e >= NE) return;
    int d = g_dst[e];
    int pos = g_off[d] + atomicAdd(&g_fill[d], 1);
    g_csr[pos] = g_src[e];
}

// ---------------- pack all 3 layers' weights (bf16 hi/lo split, K-major) ----------------
__global__ void pack_all_kernel(const float* __restrict__ Wr0, const float* __restrict__ Ws0,
                                const float* __restrict__ Wr1, const float* __restrict__ Ws1,
                                const float* __restrict__ Wr2, const float* __restrict__ Ws2) {
    int i = blockIdx.x * blockDim.x + threadIdx.x;
    if (i >= 640 * 128) return;
    const float *Wr, *Ws;
    int doh, base;
    if (i < 32768)      { Wr = Wr0; Ws = Ws0; doh = 128; base = 0; }
    else if (i < 65536) { Wr = Wr1; Ws = Ws1; doh = 128; base = 32768; }
    else                { Wr = Wr2; Ws = Ws2; doh = 64;  base = 65536; }
    int j = i - base;
    int n = j >> 7, k = j & 127;
    float w = (n < doh) ? Wr[k * doh + n] : Ws[k * doh + (n - doh)];
    __nv_bfloat16 h = __float2bfloat16_rn(w);
    __nv_bfloat16 l = __float2bfloat16_rn(w - __bfloat162float(h));
    g_Bh[i] = h;
    g_Bl[i] = l;
}

// ---------------- mma.sync dual GEMM ----------------
// D[128,128] tile of [yr | base] = split-bf16( A[128,128]fp32 @ W'[128,2*doh] ).
// Per k-step: load Ahi/Alo/Bhi/Blo fragments once, issue 3 products
// (Ahi*Bhi + Alo*Bhi + Ahi*Blo; lo*lo dropped, ~2^-16).
// SMEM tiles padded to 272B rows (128+8 bf16) -> ldmatrix conflict-free
// (row stride 68 words; 8 rows hit banks 0,4,...,28 x 4 consecutive).
#define PADROW 272                       // bytes per smem tile row
#define SM_AH  0
#define SM_AL  (128 * PADROW)            // 34816
#define SM_BH  (2 * 128 * PADROW)        // 69632
#define SM_BL  (3 * 128 * PADROW)        // 104448
#define GEMM_SMEM (4 * 128 * PADROW)     // 139264

__global__ __launch_bounds__(256, 1)
void gemm_mma_kernel(const float* __restrict__ A, const float* __restrict__ bias,
                     float* __restrict__ yr, float* __restrict__ bs,
                     int doh, int bofs) {
    extern __shared__ char smem[];
    const uint32_t sb = smem_u32(smem);
    const int tid = threadIdx.x;
    const int wid = tid >> 5;
    const int lane = tid & 31;
    const int bm = blockIdx.x * 128;
    const int bn = blockIdx.y * 128;

    // ---- load A tile (fp32 -> bf16 hi/lo) ----
    for (int i = tid; i < 128 * 32; i += 256) {
        int m = i >> 5, kv = (i & 31) << 2;
        int gm = bm + m;
        float4 a;
        if (gm < NN) a = *(const float4*)(A + (size_t)gm * 128 + kv);
        else         a = make_float4(0.f, 0.f, 0.f, 0.f);
        float f[4] = {a.x, a.y, a.z, a.w};
        uint32_t hlo = 0, hhi = 0, llo = 0, lhi = 0;
        #pragma unroll
        for (int u = 0; u < 4; u++) {
            __nv_bfloat16 h = __float2bfloat16_rn(f[u]);
            __nv_bfloat16 l = __float2bfloat16_rn(f[u] - __bfloat162float(h));
            uint32_t hu = (uint32_t)__bfloat16_as_ushort(h);
            uint32_t lu = (uint32_t)__bfloat16_as_ushort(l);
            if (u < 2) { hlo |= hu << (16 * u);       llo |= lu << (16 * u); }
            else       { hhi |= hu << (16 * (u - 2)); lhi |= lu << (16 * (u - 2)); }
        }
        uint32_t off = (uint32_t)(m * PADROW + kv * 2);     // 8B-aligned
        *(uint2*)(smem + SM_AH + off) = make_uint2(hlo, hhi);
        *(uint2*)(smem + SM_AL + off) = make_uint2(llo, lhi);
    }

    // ---- load B tiles (bf16 hi/lo, [n][k] K-major) ----
    const __nv_bfloat16* Bh = g_Bh + bofs;
    const __nv_bfloat16* Bl = g_Bl + bofs;
    for (int i = tid; i < 128 * 16; i += 256) {
        int n = i >> 4, kv = (i & 15) << 3;
        size_t gidx = (size_t)(bn + n) * 128 + kv;
        uint32_t off = (uint32_t)(n * PADROW + kv * 2);     // 16B-aligned (272=17*16)
        *(uint4*)(smem + SM_BH + off) = *(const uint4*)((const char*)Bh + gidx * 2);
        *(uint4*)(smem + SM_BL + off) = *(const uint4*)((const char*)Bl + gidx * 2);
    }
    __syncthreads();

    // ---- warp tiling: 4x2 warps, warp tile 32x64 ----
    const int warp_m = wid & 3;          // 32-row band
    const int warp_n = wid >> 2;         // 64-col band

    // ldmatrix lane offsets (bytes within a tile)
    // A x4: quadrants (m0-7,k0-7),(m8-15,k0-7),(m0-7,k8-15),(m8-15,k8-15)
    const int ra = (lane & 7) + ((lane >> 3) & 1) * 8;
    const int ka = (lane >> 4) * 8;
    uint32_t a_off[2];
    #pragma unroll
    for (int mt = 0; mt < 2; mt++)
        a_off[mt] = (uint32_t)((warp_m * 32 + mt * 16 + ra) * PADROW + ka * 2);
    // B x4: (n0-7,k0-7),(n0-7,k8-15),(n8-15,k0-7),(n8-15,k8-15)
    const int rb = (lane & 7) + (lane >> 4) * 8;
    const int kb = ((lane >> 3) & 1) * 8;
    uint32_t b_off[4];
    #pragma unroll
    for (int q = 0; q < 4; q++)
        b_off[q] = (uint32_t)((warp_n * 64 + q * 16 + rb) * PADROW + kb * 2);

    float d[2][8][4];
    #pragma unroll
    for (int mt = 0; mt < 2; mt++)
        #pragma unroll
        for (int nt = 0; nt < 8; nt++)
            #pragma unroll
            for (int u = 0; u < 4; u++) d[mt][nt][u] = 0.f;

    const uint32_t ah = sb + SM_AH, al = sb + SM_AL;
    const uint32_t bh = sb + SM_BH, bl = sb + SM_BL;

    #pragma unroll
    for (int ks = 0; ks < 8; ks++) {
        uint32_t kbyte = (uint32_t)ks * 32;
        uint32_t afh[2][4], afl[2][4], bfh[4][4], bfl[4][4];
        #pragma unroll
        for (int mt = 0; mt < 2; mt++) {
            ldsm4(afh[mt][0], afh[mt][1], afh[mt][2], afh[mt][3],
                  ah + a_off[mt] + kbyte);
            ldsm4(afl[mt][0], afl[mt][1], afl[mt][2], afl[mt][3],
                  al + a_off[mt] + kbyte);
        }
        #pragma unroll
        for (int q = 0; q < 4; q++) {
            ldsm4(bfh[q][0], bfh[q][1], bfh[q][2], bfh[q][3],
                  bh + b_off[q] + kbyte);
            ldsm4(bfl[q][0], bfl[q][1], bfl[q][2], bfl[q][3],
                  bl + b_off[q] + kbyte);
        }
        #pragma unroll
        for (int mt = 0; mt < 2; mt++)
            #pragma unroll
            for (int nt = 0; nt < 8; nt++) {
                int q = nt >> 1, h = (nt & 1) * 2;
                mma_bf16(d[mt][nt], afh[mt], bfh[q][h], bfh[q][h + 1]);
                mma_bf16(d[mt][nt], afl[mt], bfh[q][h], bfh[q][h + 1]);
                mma_bf16(d[mt][nt], afh[mt], bfl[q][h], bfl[q][h + 1]);
            }
    }

    // ---- epilogue: thread owns rows (tq, tq+8), col pair 2*tr per tile ----
    const int tq = lane >> 2, tr = lane & 3;
    #pragma unroll
    for (int mt = 0; mt < 2; mt++) {
        int r0 = bm + warp_m * 32 + mt * 16 + tq;
        int r1 = r0 + 8;
        #pragma unroll
        for (int nt = 0; nt < 8; nt++) {
            int col = bn + warp_n * 64 + nt * 8 + tr * 2;
            float2 v0 = make_float2(d[mt][nt][0], d[mt][nt][1]);
            float2 v1 = make_float2(d[mt][nt][2], d[mt][nt][3]);
            if (col < doh) {
                if (r0 < NN) *(float2*)(yr + (size_t)r0 * doh + col) = v0;
                if (r1 < NN) *(float2*)(yr + (size_t)r1 * doh + col) = v1;
            } else {
                int c = col - doh;
                float bx = bias[c], by = bias[c + 1];
                v0.x += bx; v0.y += by; v1.x += bx; v1.y += by;
                if (r0 < NN) *(float2*)(bs + (size_t)r0 * doh + c) = v0;
                if (r1 < NN) *(float2*)(bs + (size_t)r1 * doh + c) = v1;
            }
        }
    }
}

// ---------------- aggregation: out = relu(base + sum_{j in N(i)} yr[j]) ----------------
template <int DO, bool FINAL>
__global__ __launch_bounds__(256)
void agg_kernel(float* __restrict__ out) {
    int w = (blockIdx.x * blockDim.x + threadIdx.x) >> 5;
    int lane = threadIdx.x & 31;
    if (w >= NN) return;
    int e  = g_off[w];
    int e1 = g_off[w + 1];

    if (DO == 128) {
        float4 acc = *(const float4*)(g_base + (size_t)w * 128 + (lane << 2));
        // 8-wide: MLP=8 independent row gathers in flight
        for (; e + 7 < e1; e += 8) {
            float4 acc2 = make_float4(0.f, 0.f, 0.f, 0.f);
            int idx[8];
            #pragma unroll
            for (int u = 0; u < 8; u++) idx[u] = g_csr[e + u];
            float4 v[8];
            #pragma unroll
            for (int u = 0; u < 8; u++)
                v[u] = *(const float4*)(g_yr + (size_t)idx[u] * 128 + (lane << 2));
            #pragma unroll
            for (int u = 0; u < 8; u += 2) {
                acc.x  += v[u].x;     acc.y  += v[u].y;
                acc.z  += v[u].z;     acc.w  += v[u].w;
                acc2.x += v[u + 1].x; acc2.y += v[u + 1].y;
                acc2.z += v[u + 1].z; acc2.w += v[u + 1].w;
            }
            acc.x += acc2.x; acc.y += acc2.y; acc.z += acc2.z; acc.w += acc2.w;
        }
        for (; e + 3 < e1; e += 4) {
            int a = g_csr[e], b = g_csr[e + 1], c = g_csr[e + 2], d = g_csr[e + 3];
            float4 va = *(const float4*)(g_yr + (size_t)a * 128 + (lane << 2));
            float4 vb = *(const float4*)(g_yr + (size_t)b * 128 + (lane << 2));
            float4 vc = *(const float4*)(g_yr + (size_t)c * 128 + (lane << 2));
            float4 vd = *(const float4*)(g_yr + (size_t)d * 128 + (lane << 2));
            acc.x += (va.x + vb.x) + (vc.x + vd.x);
            acc.y += (va.y + vb.y) + (vc.y + vd.y);
            acc.z += (va.z + vb.z) + (vc.z + vd.z);
            acc.w += (va.w + vb.w) + (vc.w + vd.w);
        }
        for (; e < e1; e++) {
            int a = g_csr[e];
            float4 va = *(const float4*)(g_yr + (size_t)a * 128 + (lane << 2));
            acc.x += va.x; acc.y += va.y; acc.z += va.z; acc.w += va.w;
        }
        acc.x = fmaxf(acc.x, 0.f); acc.y = fmaxf(acc.y, 0.f);
        acc.z = fmaxf(acc.z, 0.f); acc.w = fmaxf(acc.w, 0.f);
        *(float4*)(out + (size_t)w * 128 + (lane << 2)) = acc;
    } else {
        float2 acc = *(const float2*)(g_base + (size_t)w * 64 + (lane << 1));
        // 8-wide: MLP=8 independent row gathers in flight
        for (; e + 7 < e1; e += 8) {
            float2 acc2 = make_float2(0.f, 0.f);
            int idx[8];
            #pragma unroll
            for (int u = 0; u < 8; u++) idx[u] = g_csr[e + u];
            float2 v[8];
            #pragma unroll
            for (int u = 0; u < 8; u++)
                v[u] = *(const float2*)(g_yr + (size_t)idx[u] * 64 + (lane << 1));
            #pragma unroll
            for (int u = 0; u < 8; u += 2) {
                acc.x  += v[u].x;     acc.y  += v[u].y;
                acc2.x += v[u + 1].x; acc2.y += v[u + 1].y;
            }
            acc.x += acc2.x; acc.y += acc2.y;
        }
        for (; e + 3 < e1; e += 4) {
            int a = g_csr[e], b = g_csr[e + 1], c = g_csr[e + 2], d = g_csr[e + 3];
            float2 va = *(const float2*)(g_yr + (size_t)a * 64 + (lane << 1));
            float2 vb = *(const float2*)(g_yr + (size_t)b * 64 + (lane << 1));
            float2 vc = *(const float2*)(g_yr + (size_t)c * 64 + (lane << 1));
            float2 vd = *(const float2*)(g_yr + (size_t)d * 64 + (lane << 1));
            acc.x += (va.x + vb.x) + (vc.x + vd.x);
            acc.y += (va.y + vb.y) + (vc.y + vd.y);
        }
        for (; e < e1; e++) {
            int a = g_csr[e];
            float2 va = *(const float2*)(g_yr + (size_t)a * 64 + (lane << 1));
            acc.x += va.x; acc.y += va.y;
        }
        acc.x = fmaxf(acc.x, 0.f);
        acc.y = fmaxf(acc.y, 0.f);
        if (FINAL) {
            float m = fmaxf(acc.x, acc.y);
            #pragma unroll
            for (int o = 16; o; o >>= 1)
                m = fmaxf(m, __shfl_xor_sync(0xffffffffu, m, o));
            float sm = expf(acc.x - m) + expf(acc.y - m);
            #pragma unroll
            for (int o = 16; o; o >>= 1)
                sm += __shfl_xor_sync(0xffffffffu, sm, o);
            float l = m + logf(sm);
            acc.x -= l; acc.y -= l;
        }
        *(float2*)(out + (size_t)w * 64 + (lane << 1)) = acc;
    }
}

// ---------------- host orchestration ----------------
extern "C" void kernel_launch(void* const* d_in, const int* in_sizes, int n_in,
                              void* d_out, int out_size) {
    const float* x   = (const float*)d_in[0];
    const void*  ei  = d_in[1];
    const float* Wr0 = (const float*)d_in[2];
    const float* br0 = (const float*)d_in[3];
    const float* Ws0 = (const float*)d_in[4];
    const float* Wr1 = (const float*)d_in[5];
    const float* br1 = (const float*)d_in[6];
    const float* Ws1 = (const float*)d_in[7];
    const float* Wr2 = (const float*)d_in[8];
    const float* br2 = (const float*)d_in[9];
    const float* Ws2 = (const float*)d_in[10];
    float* out = (float*)d_out;

    void *p_h, *p_yr, *p_base;
    cudaGetSymbolAddress(&p_h, g_h);
    cudaGetSymbolAddress(&p_yr, g_yr);
    cudaGetSymbolAddress(&p_base, g_base);
    float* hbuf  = (float*)p_h;
    float* yrbuf = (float*)p_yr;
    float* bsbuf = (float*)p_base;

    cudaFuncSetAttribute(gemm_mma_kernel,
                         cudaFuncAttributeMaxDynamicSharedMemorySize, GEMM_SMEM);

    const int EB = (NE + 255) / 256;
    const int NB = (NN + 255) / 256;
    const int MT = (NN + 127) / 128;   // 313 M-tiles

    // weight pack (independent of graph build)
    pack_all_kernel<<<(640 * 128 + 255) / 256, 256>>>(Wr0, Ws0, Wr1, Ws1, Wr2, Ws2);

    // edge index -> int32 src/dst + degree histogram
    detect_kernel<<<1, 32>>>((const int*)ei);
    zero_kernel<<<NB, 256>>>();
    convert_hist_kernel<<<EB, 256>>>(ei);
    scan_kernel<<<1, 1024>>>();
    fill_kernel<<<EB, 256>>>();

    // ---- layer 0: x -> h (d=128) ----
    gemm_mma_kernel<<<dim3(MT, 2), 256, GEMM_SMEM>>>(x, br0, yrbuf, bsbuf, 128, 0);
    agg_kernel<128, false><<<(NN * 32 + 255) / 256, 256>>>(hbuf);

    // ---- layer 1: h -> h (d=128) ----
    gemm_mma_kernel<<<dim3(MT, 2), 256, GEMM_SMEM>>>(hbuf, br1, yrbuf, bsbuf, 128, 32768);
    agg_kernel<128, false><<<(NN * 32 + 255) / 256, 256>>>(hbuf);

    // ---- layer 2: h -> out (d=64), fused relu + log_softmax ----
    gemm_mma_kernel<<<dim3(MT, 1), 256, GEMM_SMEM>>>(hbuf, br2, yrbuf, bsbuf, 64, 65536);
    agg_kernel<64, true><<<(NN * 32 + 255) / 256, 256>>>(out);
}

// round 14
// speedup vs baseline: 1.0574x; 1.0574x over previous
#include <cuda_runtime.h>
#include <cuda_bf16.h>
#include <cuda_fp16.h>
#include <math.h>
#include <stdint.h>

#define NN 40000
#define NE 640000

// ---------------- scratch (device globals: allocation-free) ----------------
__device__ int    g_is64;
__device__ int    g_src[NE];
__device__ int    g_dst[NE];
__device__ int    g_csr[NE];
__device__ int    g_deg[NN];
__device__ int    g_fill[NN];
__device__ int    g_off[NN + 1];
__device__ float  g_h[NN * 128];
__device__ __half g_yr[NN * 128];      // fp16: halves the agg gather traffic
__device__ float  g_base[NN * 128];
// packed weights, all 3 layers: [n][k] K-major bf16 hi/lo
// region offsets (elements): L0=0 (256 rows), L1=32768 (256 rows), L2=65536 (128 rows)
__device__ __nv_bfloat16 g_Bh[640 * 128];
__device__ __nv_bfloat16 g_Bl[640 * 128];

// ---------------- helpers ----------------
__device__ __forceinline__ uint32_t smem_u32(const void* p) {
    uint32_t a;
    asm("{ .reg .u64 t; cvta.to.shared.u64 t, %1; cvt.u32.u64 %0, t; }"
        : "=r"(a) : "l"(p));
    return a;
}

__device__ __forceinline__ void ldsm4(uint32_t& r0, uint32_t& r1,
                                      uint32_t& r2, uint32_t& r3, uint32_t addr) {
    asm volatile("ldmatrix.sync.aligned.m8n8.x4.shared.b16 {%0,%1,%2,%3}, [%4];"
                 : "=r"(r0), "=r"(r1), "=r"(r2), "=r"(r3) : "r"(addr));
}

__device__ __forceinline__ void mma_bf16(float* d, const uint32_t* a,
                                         uint32_t b0, uint32_t b1) {
    asm volatile(
        "mma.sync.aligned.m16n8k16.row.col.f32.bf16.bf16.f32 "
        "{%0,%1,%2,%3}, {%4,%5,%6,%7}, {%8,%9}, {%0,%1,%2,%3};"
        : "+f"(d[0]), "+f"(d[1]), "+f"(d[2]), "+f"(d[3])
        : "r"(a[0]), "r"(a[1]), "r"(a[2]), "r"(a[3]), "r"(b0), "r"(b1));
}

// ---------------- edge dtype detection ----------------
// int64 little-endian with values < 40000 -> every odd 32-bit word is 0.
__global__ void detect_kernel(const int* __restrict__ e32) {
    if (threadIdx.x == 0) {
        int ok = 1;
        for (int i = 0; i < 64; i++)
            if (e32[2 * i + 1] != 0) { ok = 0; break; }
        g_is64 = ok;
    }
}

__global__ void zero_kernel() {
    int i = blockIdx.x * blockDim.x + threadIdx.x;
    if (i < NN) { g_deg[i] = 0; g_fill[i] = 0; }
}

// convert + histogram fused (zero_kernel must precede)
__global__ void convert_hist_kernel(const void* __restrict__ ei) {
    int e = blockIdx.x * blockDim.x + threadIdx.x;
    if (e >= NE) return;
    int s, d;
    if (g_is64) {
        const long long* p = (const long long*)ei;
        s = (int)p[e]; d = (int)p[NE + e];
    } else {
        const int* p = (const int*)ei;
        s = p[e]; d = p[NE + e];
    }
    g_src[e] = s;
    g_dst[e] = d;
    atomicAdd(&g_deg[d], 1);
}

// shfl-based exclusive scan over g_deg -> g_off (single block, 1024 threads)
__global__ void scan_kernel() {
    __shared__ int wsum[32];
    __shared__ int carry_s;
    int t = threadIdx.x, lane = t & 31, wi = t >> 5;
    if (t == 0) carry_s = 0;
    __syncthreads();
    for (int base = 0; base < NN; base += 1024) {
        int v = (base + t < NN) ? g_deg[base + t] : 0;
        int x = v;
        #pragma unroll
        for (int o = 1; o < 32; o <<= 1) {
            int y = __shfl_up_sync(0xffffffffu, x, o);
            if (lane >= o) x += y;
        }
        if (lane == 31) wsum[wi] = x;
        __syncthreads();                       // S1: wsum[] published
        if (wi == 0) {
            int s = wsum[lane];
            #pragma unroll
            for (int o = 1; o < 32; o <<= 1) {
                int y = __shfl_up_sync(0xffffffffu, s, o);
                if (lane >= o) s += y;
            }
            wsum[lane] = s;                    // inclusive scan of warp sums
        }
        __syncthreads();                       // S2: scanned wsum published
        int warpoff = (wi > 0) ? wsum[wi - 1] : 0;
        int carry = carry_s;
        if (base + t < NN) g_off[base + t] = carry + warpoff + x - v;
        __syncthreads();                       // S3: all reads done
        if (t == 1023) carry_s = carry + wsum[31];
        __syncthreads();                       // S4: carry visible, wsum reusable
    }
    if (threadIdx.x == 0) g_off[NN] = carry_s;
}

__global__ void fill_kernel() {
    int e = blockIdx.x * blockDim.x + threadIdx.x;
    if (e >= NE) return;
    int d = g_dst[e];
    int pos = g_off[d] + atomicAdd(&g_fill[d], 1);
    g_csr[pos] = g_src[e];
}

// ---------------- pack all 3 layers' weights (bf16 hi/lo split, K-major) ----------------
__global__ void pack_all_kernel(const float* __restrict__ Wr0, const float* __restrict__ Ws0,
                                const float* __restrict__ Wr1, const float* __restrict__ Ws1,
                                const float* __restrict__ Wr2, const float* __restrict__ Ws2) {
    int i = blockIdx.x * blockDim.x + threadIdx.x;
    if (i >= 640 * 128) return;
    const float *Wr, *Ws;
    int doh, base;
    if (i < 32768)      { Wr = Wr0; Ws = Ws0; doh = 128; base = 0; }
    else if (i < 65536) { Wr = Wr1; Ws = Ws1; doh = 128; base = 32768; }
    else                { Wr = Wr2; Ws = Ws2; doh = 64;  base = 65536; }
    int j = i - base;
    int n = j >> 7, k = j & 127;
    float w = (n < doh) ? Wr[k * doh + n] : Ws[k * doh + (n - doh)];
    __nv_bfloat16 h = __float2bfloat16_rn(w);
    __nv_bfloat16 l = __float2bfloat16_rn(w - __bfloat162float(h));
    g_Bh[i] = h;
    g_Bl[i] = l;
}

// ---------------- mma.sync dual GEMM ----------------
// D[128,128] tile of [yr | base] = split-bf16( A[128,128]fp32 @ W'[128,2*doh] ).
// Per k-step: load Ahi/Alo/Bhi/Blo fragments once, issue 3 products
// (Ahi*Bhi + Alo*Bhi + Ahi*Blo; lo*lo dropped, ~2^-16).
// yr written fp16 (gather-traffic optimization); base written fp32 + bias.
// SMEM tiles padded to 272B rows (128+8 bf16) -> ldmatrix conflict-free.
#define PADROW 272                       // bytes per smem tile row
#define SM_AH  0
#define SM_AL  (128 * PADROW)            // 34816
#define SM_BH  (2 * 128 * PADROW)        // 69632
#define SM_BL  (3 * 128 * PADROW)        // 104448
#define GEMM_SMEM (4 * 128 * PADROW)     // 139264

__global__ __launch_bounds__(256, 1)
void gemm_mma_kernel(const float* __restrict__ A, const float* __restrict__ bias,
                     __half* __restrict__ yr, float* __restrict__ bs,
                     int doh, int bofs) {
    extern __shared__ char smem[];
    const uint32_t sb = smem_u32(smem);
    const int tid = threadIdx.x;
    const int wid = tid >> 5;
    const int lane = tid & 31;
    const int bm = blockIdx.x * 128;
    const int bn = blockIdx.y * 128;

    // ---- load A tile (fp32 -> bf16 hi/lo) ----
    for (int i = tid; i < 128 * 32; i += 256) {
        int m = i >> 5, kv = (i & 31) << 2;
        int gm = bm + m;
        float4 a;
        if (gm < NN) a = *(const float4*)(A + (size_t)gm * 128 + kv);
        else         a = make_float4(0.f, 0.f, 0.f, 0.f);
        float f[4] = {a.x, a.y, a.z, a.w};
        uint32_t hlo = 0, hhi = 0, llo = 0, lhi = 0;
        #pragma unroll
        for (int u = 0; u < 4; u++) {
            __nv_bfloat16 h = __float2bfloat16_rn(f[u]);
            __nv_bfloat16 l = __float2bfloat16_rn(f[u] - __bfloat162float(h));
            uint32_t hu = (uint32_t)__bfloat16_as_ushort(h);
            uint32_t lu = (uint32_t)__bfloat16_as_ushort(l);
            if (u < 2) { hlo |= hu << (16 * u);       llo |= lu << (16 * u); }
            else       { hhi |= hu << (16 * (u - 2)); lhi |= lu << (16 * (u - 2)); }
        }
        uint32_t off = (uint32_t)(m * PADROW + kv * 2);     // 8B-aligned
        *(uint2*)(smem + SM_AH + off) = make_uint2(hlo, hhi);
        *(uint2*)(smem + SM_AL + off) = make_uint2(llo, lhi);
    }

    // ---- load B tiles (bf16 hi/lo, [n][k] K-major) ----
    const __nv_bfloat16* Bh = g_Bh + bofs;
    const __nv_bfloat16* Bl = g_Bl + bofs;
    for (int i = tid; i < 128 * 16; i += 256) {
        int n = i >> 4, kv = (i & 15) << 3;
        size_t gidx = (size_t)(bn + n) * 128 + kv;
        uint32_t off = (uint32_t)(n * PADROW + kv * 2);     // 16B-aligned (272=17*16)
        *(uint4*)(smem + SM_BH + off) = *(const uint4*)((const char*)Bh + gidx * 2);
        *(uint4*)(smem + SM_BL + off) = *(const uint4*)((const char*)Bl + gidx * 2);
    }
    __syncthreads();

    // ---- warp tiling: 4x2 warps, warp tile 32x64 ----
    const int warp_m = wid & 3;          // 32-row band
    const int warp_n = wid >> 2;         // 64-col band

    // ldmatrix lane offsets (bytes within a tile)
    // A x4: quadrants (m0-7,k0-7),(m8-15,k0-7),(m0-7,k8-15),(m8-15,k8-15)
    const int ra = (lane & 7) + ((lane >> 3) & 1) * 8;
    const int ka = (lane >> 4) * 8;
    uint32_t a_off[2];
    #pragma unroll
    for (int mt = 0; mt < 2; mt++)
        a_off[mt] = (uint32_t)((warp_m * 32 + mt * 16 + ra) * PADROW + ka * 2);
    // B x4: (n0-7,k0-7),(n0-7,k8-15),(n8-15,k0-7),(n8-15,k8-15)
    const int rb = (lane & 7) + (lane >> 4) * 8;
    const int kb = ((lane >> 3) & 1) * 8;
    uint32_t b_off[4];
    #pragma unroll
    for (int q = 0; q < 4; q++)
        b_off[q] = (uint32_t)((warp_n * 64 + q * 16 + rb) * PADROW + kb * 2);

    float d[2][8][4];
    #pragma unroll
    for (int mt = 0; mt < 2; mt++)
        #pragma unroll
        for (int nt = 0; nt < 8; nt++)
            #pragma unroll
            for (int u = 0; u < 4; u++) d[mt][nt][u] = 0.f;

    const uint32_t ah = sb + SM_AH, al = sb + SM_AL;
    const uint32_t bh = sb + SM_BH, bl = sb + SM_BL;

    #pragma unroll
    for (int ks = 0; ks < 8; ks++) {
        uint32_t kbyte = (uint32_t)ks * 32;
        uint32_t afh[2][4], afl[2][4], bfh[4][4], bfl[4][4];
        #pragma unroll
        for (int mt = 0; mt < 2; mt++) {
            ldsm4(afh[mt][0], afh[mt][1], afh[mt][2], afh[mt][3],
                  ah + a_off[mt] + kbyte);
            ldsm4(afl[mt][0], afl[mt][1], afl[mt][2], afl[mt][3],
                  al + a_off[mt] + kbyte);
        }
        #pragma unroll
        for (int q = 0; q < 4; q++) {
            ldsm4(bfh[q][0], bfh[q][1], bfh[q][2], bfh[q][3],
                  bh + b_off[q] + kbyte);
            ldsm4(bfl[q][0], bfl[q][1], bfl[q][2], bfl[q][3],
                  bl + b_off[q] + kbyte);
        }
        #pragma unroll
        for (int mt = 0; mt < 2; mt++)
            #pragma unroll
            for (int nt = 0; nt < 8; nt++) {
                int q = nt >> 1, h = (nt & 1) * 2;
                mma_bf16(d[mt][nt], afh[mt], bfh[q][h], bfh[q][h + 1]);
                mma_bf16(d[mt][nt], afl[mt], bfh[q][h], bfh[q][h + 1]);
                mma_bf16(d[mt][nt], afh[mt], bfl[q][h], bfl[q][h + 1]);
            }
    }

    // ---- epilogue: thread owns rows (tq, tq+8), col pair 2*tr per tile ----
    const int tq = lane >> 2, tr = lane & 3;
    #pragma unroll
    for (int mt = 0; mt < 2; mt++) {
        int r0 = bm + warp_m * 32 + mt * 16 + tq;
        int r1 = r0 + 8;
        #pragma unroll
        for (int nt = 0; nt < 8; nt++) {
            int col = bn + warp_n * 64 + nt * 8 + tr * 2;
            float2 v0 = make_float2(d[mt][nt][0], d[mt][nt][1]);
            float2 v1 = make_float2(d[mt][nt][2], d[mt][nt][3]);
            if (col < doh) {
                __half2 h0 = __float22half2_rn(v0);
                __half2 h1 = __float22half2_rn(v1);
                if (r0 < NN) *(__half2*)(yr + (size_t)r0 * doh + col) = h0;
                if (r1 < NN) *(__half2*)(yr + (size_t)r1 * doh + col) = h1;
            } else {
                int c = col - doh;
                float bx = bias[c], by = bias[c + 1];
                v0.x += bx; v0.y += by; v1.x += bx; v1.y += by;
                if (r0 < NN) *(float2*)(bs + (size_t)r0 * doh + c) = v0;
                if (r1 < NN) *(float2*)(bs + (size_t)r1 * doh + c) = v1;
            }
        }
    }
}

// ---------------- aggregation: out = relu(base + sum_{j in N(i)} yr[j]) ----------------
// yr is fp16 (gathered per edge, fp32 accumulation); base/out are fp32.
template <int DO, bool FINAL>
__global__ __launch_bounds__(256)
void agg_kernel(float* __restrict__ out) {
    int w = (blockIdx.x * blockDim.x + threadIdx.x) >> 5;
    int lane = threadIdx.x & 31;
    if (w >= NN) return;
    int e  = g_off[w];
    int e1 = g_off[w + 1];

    if (DO == 128) {
        float4 acc = *(const float4*)(g_base + (size_t)w * 128 + (lane << 2));
        // 8-wide: MLP=8 independent row gathers in flight
        for (; e + 7 < e1; e += 8) {
            float4 acc2 = make_float4(0.f, 0.f, 0.f, 0.f);
            int idx[8];
            #pragma unroll
            for (int u = 0; u < 8; u++) idx[u] = g_csr[e + u];
            uint2 v[8];
            #pragma unroll
            for (int u = 0; u < 8; u++)
                v[u] = *(const uint2*)(g_yr + (size_t)idx[u] * 128 + (lane << 2));
            #pragma unroll
            for (int u = 0; u < 8; u += 2) {
                float2 a0 = __half22float2(*(const __half2*)&v[u].x);
                float2 a1 = __half22float2(*(const __half2*)&v[u].y);
                float2 b0 = __half22float2(*(const __half2*)&v[u + 1].x);
                float2 b1 = __half22float2(*(const __half2*)&v[u + 1].y);
                acc.x  += a0.x; acc.y  += a0.y; acc.z  += a1.x; acc.w  += a1.y;
                acc2.x += b0.x; acc2.y += b0.y; acc2.z += b1.x; acc2.w += b1.y;
            }
            acc.x += acc2.x; acc.y += acc2.y; acc.z += acc2.z; acc.w += acc2.w;
        }
        for (; e < e1; e++) {
            uint2 v = *(const uint2*)(g_yr + (size_t)g_csr[e] * 128 + (lane << 2));
            float2 a0 = __half22float2(*(const __half2*)&v.x);
            float2 a1 = __half22float2(*(const __half2*)&v.y);
            acc.x += a0.x; acc.y += a0.y; acc.z += a1.x; acc.w += a1.y;
        }
        acc.x = fmaxf(acc.x, 0.f); acc.y = fmaxf(acc.y, 0.f);
        acc.z = fmaxf(acc.z, 0.f); acc.w = fmaxf(acc.w, 0.f);
        *(float4*)(out + (size_t)w * 128 + (lane << 2)) = acc;
    } else {
        float2 acc = *(const float2*)(g_base + (size_t)w * 64 + (lane << 1));
        // 8-wide: MLP=8 independent row gathers in flight
        for (; e + 7 < e1; e += 8) {
            float2 acc2 = make_float2(0.f, 0.f);
            int idx[8];
            #pragma unroll
            for (int u = 0; u < 8; u++) idx[u] = g_csr[e + u];
            uint32_t v[8];
            #pragma unroll
            for (int u = 0; u < 8; u++)
                v[u] = *(const uint32_t*)(g_yr + (size_t)idx[u] * 64 + (lane << 1));
            #pragma unroll
            for (int u = 0; u < 8; u += 2) {
                float2 a = __half22float2(*(const __half2*)&v[u]);
                float2 b = __half22float2(*(const __half2*)&v[u + 1]);
                acc.x  += a.x; acc.y  += a.y;
                acc2.x += b.x; acc2.y += b.y;
            }
            acc.x += acc2.x; acc.y += acc2.y;
        }
        for (; e < e1; e++) {
            uint32_t v = *(const uint32_t*)(g_yr + (size_t)g_csr[e] * 64 + (lane << 1));
            float2 a = __half22float2(*(const __half2*)&v);
            acc.x += a.x; acc.y += a.y;
        }
        acc.x = fmaxf(acc.x, 0.f);
        acc.y = fmaxf(acc.y, 0.f);
        if (FINAL) {
            float m = fmaxf(acc.x, acc.y);
            #pragma unroll
            for (int o = 16; o; o >>= 1)
                m = fmaxf(m, __shfl_xor_sync(0xffffffffu, m, o));
            float sm = expf(acc.x - m) + expf(acc.y - m);
            #pragma unroll
            for (int o = 16; o; o >>= 1)
                sm += __shfl_xor_sync(0xffffffffu, sm, o);
            float l = m + logf(sm);
            acc.x -= l; acc.y -= l;
        }
        *(float2*)(out + (size_t)w * 64 + (lane << 1)) = acc;
    }
}

// ---------------- host orchestration ----------------
extern "C" void kernel_launch(void* const* d_in, const int* in_sizes, int n_in,
                              void* d_out, int out_size) {
    const float* x   = (const float*)d_in[0];
    const void*  ei  = d_in[1];
    const float* Wr0 = (const float*)d_in[2];
    const float* br0 = (const float*)d_in[3];
    const float* Ws0 = (const float*)d_in[4];
    const float* Wr1 = (const float*)d_in[5];
    const float* br1 = (const float*)d_in[6];
    const float* Ws1 = (const float*)d_in[7];
    const float* Wr2 = (const float*)d_in[8];
    const float* br2 = (const float*)d_in[9];
    const float* Ws2 = (const float*)d_in[10];
    float* out = (float*)d_out;

    void *p_h, *p_yr, *p_base;
    cudaGetSymbolAddress(&p_h, g_h);
    cudaGetSymbolAddress(&p_yr, g_yr);
    cudaGetSymbolAddress(&p_base, g_base);
    float*  hbuf  = (float*)p_h;
    __half* yrbuf = (__half*)p_yr;
    float*  bsbuf = (float*)p_base;

    cudaFuncSetAttribute(gemm_mma_kernel,
                         cudaFuncAttributeMaxDynamicSharedMemorySize, GEMM_SMEM);

    const int EB = (NE + 255) / 256;
    const int NB = (NN + 255) / 256;
    const int MT = (NN + 127) / 128;   // 313 M-tiles

    // weight pack (independent of graph build)
    pack_all_kernel<<<(640 * 128 + 255) / 256, 256>>>(Wr0, Ws0, Wr1, Ws1, Wr2, Ws2);

    // edge index -> int32 src/dst + degree histogram
    detect_kernel<<<1, 32>>>((const int*)ei);
    zero_kernel<<<NB, 256>>>();
    convert_hist_kernel<<<EB, 256>>>(ei);
    scan_kernel<<<1, 1024>>>();
    fill_kernel<<<EB, 256>>>();

    // ---- layer 0: x -> h (d=128) ----
    gemm_mma_kernel<<<dim3(MT, 2), 256, GEMM_SMEM>>>(x, br0, yrbuf, bsbuf, 128, 0);
    agg_kernel<128, false><<<(NN * 32 + 255) / 256, 256>>>(hbuf);

    // ---- layer 1: h -> h (d=128) ----
    gemm_mma_kernel<<<dim3(MT, 2), 256, GEMM_SMEM>>>(hbuf, br1, yrbuf, bsbuf, 128, 32768);
    agg_kernel<128, false><<<(NN * 32 + 255) / 256, 256>>>(hbuf);

    // ---- layer 2: h -> out (d=64), fused relu + log_softmax ----
    gemm_mma_kernel<<<dim3(MT, 1), 256, GEMM_SMEM>>>(hbuf, br2, yrbuf, bsbuf, 64, 65536);
    agg_kernel<64, true><<<(NN * 32 + 255) / 256, 256>>>(out);
}